// round 13
// baseline (speedup 1.0000x reference)
#include <cuda_runtime.h>
#include <cuda_bf16.h>
#include <cstdint>
#include <math.h>

#define BATCH 8
#define CH    512
#define CH3   1536
#define HH    64
#define NPIX  4096          // 64*64
#define WR    33            // rfft width 64/2+1
#define FREQ  2112          // 64*33
#define PLANES (BATCH*CH)   // 4096
#define NQKV  4224          // 2*FREQ floats per plane-row (interleaved complex)

#define W_GATE_OFF 0
#define W_QKV_OFF  (CH*CH)
#define W_PROJ_OFF (CH*CH + CH3*CH)
#define W_TOTAL    (2*CH*CH + CH3*CH)

// ---- static scratch (no allocations allowed) ----
__device__ float2 g_Qc[BATCH*CH3*FREQ];   // interleaved {re,im}
__device__ float  g_t[BATCH*CH*NPIX];
__device__ __nv_bfloat16 g_wh[W_TOTAL];
__device__ __nv_bfloat16 g_wl[W_TOTAL];
__device__ __nv_bfloat16 g_bh[BATCH*CH*NQKV];    // x-split / y-split
__device__ __nv_bfloat16 g_bl[BATCH*CH*NQKV];
__device__ __nv_bfloat16 g_b2h[BATCH*CH*NQKV];   // spectrum split
__device__ __nv_bfloat16 g_b2l[BATCH*CH*NQKV];

#define TWO_PI_OVER_64 0.09817477042468103f

// ---- cp.async helpers ----
__device__ __forceinline__ void cp_async16(unsigned int saddr, const void* g) {
    asm volatile("cp.async.cg.shared.global [%0], [%1], 16;\n" :: "r"(saddr), "l"(g));
}
__device__ __forceinline__ void cp_commit() { asm volatile("cp.async.commit_group;\n"); }
__device__ __forceinline__ void cp_wait0()  { asm volatile("cp.async.wait_group 0;\n" ::: "memory"); }

// ---- tensor-core helpers ----
__device__ __forceinline__ void mma16816(float* d, const unsigned* a, const unsigned* b) {
    asm volatile("mma.sync.aligned.m16n8k16.row.col.f32.bf16.bf16.f32 "
        "{%0,%1,%2,%3}, {%4,%5,%6,%7}, {%8,%9}, {%0,%1,%2,%3};"
        : "+f"(d[0]), "+f"(d[1]), "+f"(d[2]), "+f"(d[3])
        : "r"(a[0]), "r"(a[1]), "r"(a[2]), "r"(a[3]), "r"(b[0]), "r"(b[1]));
}
__device__ __forceinline__ void ldsm4(unsigned* r, unsigned addr) {
    asm volatile("ldmatrix.sync.aligned.m8n8.x4.shared.b16 {%0,%1,%2,%3}, [%4];"
        : "=r"(r[0]), "=r"(r[1]), "=r"(r[2]), "=r"(r[3]) : "r"(addr));
}
__device__ __forceinline__ void ldsm4t(unsigned* r, unsigned addr) {
    asm volatile("ldmatrix.sync.aligned.m8n8.x4.trans.shared.b16 {%0,%1,%2,%3}, [%4];"
        : "=r"(r[0]), "=r"(r[1]), "=r"(r[2]), "=r"(r[3]) : "r"(addr));
}

// ---- bf16 hi/lo split store of a float2 ----
__device__ __forceinline__ void split_store2(__nv_bfloat162* __restrict__ h,
                                             __nv_bfloat162* __restrict__ l,
                                             size_t idx, float2 v) {
    __nv_bfloat16 hx = __float2bfloat16(v.x);
    __nv_bfloat16 hy = __float2bfloat16(v.y);
    __nv_bfloat162 H, L;
    H.x = hx; H.y = hy;
    L.x = __float2bfloat16(v.x - __bfloat162float(hx));
    L.y = __float2bfloat16(v.y - __bfloat162float(hy));
    h[idx] = H; l[idx] = L;
}

// ---- complex helpers ----
__device__ __forceinline__ float2 cadd(float2 a, float2 b){ return make_float2(a.x+b.x, a.y+b.y); }
__device__ __forceinline__ float2 csub(float2 a, float2 b){ return make_float2(a.x-b.x, a.y-b.y); }
__device__ __forceinline__ float2 cmul(float2 a, float2 t){ return make_float2(a.x*t.x - a.y*t.y, a.x*t.y + a.y*t.x); }

template<int S>
__device__ __forceinline__ float2 muliS(float2 a) {
    return (S > 0) ? make_float2(-a.y, a.x) : make_float2(a.y, -a.x);
}

template<int S>
__device__ __forceinline__ void dft8(float2 z[8]) {
    const float C = 0.70710678118654752f;
    const float sf = (S > 0) ? 1.f : -1.f;
    float2 t0 = cadd(z[0], z[4]), t1 = csub(z[0], z[4]);
    float2 t2 = cadd(z[2], z[6]), t3 = csub(z[2], z[6]);
    float2 E0 = cadd(t0, t2), E2 = csub(t0, t2);
    float2 t3r = muliS<S>(t3);
    float2 E1 = cadd(t1, t3r), E3 = csub(t1, t3r);
    float2 s0 = cadd(z[1], z[5]), s1 = csub(z[1], z[5]);
    float2 s2 = cadd(z[3], z[7]), s3 = csub(z[3], z[7]);
    float2 O0 = cadd(s0, s2), O2 = csub(s0, s2);
    float2 s3r = muliS<S>(s3);
    float2 O1 = cadd(s1, s3r), O3 = csub(s1, s3r);
    float2 W1O1 = make_float2(C*(O1.x - sf*O1.y), C*(O1.y + sf*O1.x));
    float2 W2O2 = muliS<S>(O2);
    float2 W3O3 = make_float2(C*(-O3.x - sf*O3.y), C*(-O3.y + sf*O3.x));
    z[0] = cadd(E0, O0);  z[4] = csub(E0, O0);
    z[1] = cadd(E1, W1O1); z[5] = csub(E1, W1O1);
    z[2] = cadd(E2, W2O2); z[6] = csub(E2, W2O2);
    z[3] = cadd(E3, W3O3); z[7] = csub(E3, W3O3);
}

// ============================================================
// Warp-cooperative 64-pt FFT phases.
// ============================================================
__device__ __forceinline__ void ifft_cols(const float2* __restrict__ y2, float2* __restrict__ u2,
                                          const float2* Ti, int tid)
{
    const int g = tid >> 3, sub = tid & 7;
    float2 z[8];
    if (g == 0) {
        #pragma unroll
        for (int n1 = 0; n1 < 8; n1++) {
            int m = 8*n1 + sub;
            float2 A = y2[33*m], B = y2[33*m + 32];
            z[n1] = make_float2(A.x - B.y, A.y + B.x);
        }
    } else {
        #pragma unroll
        for (int n1 = 0; n1 < 8; n1++) z[n1] = y2[33*(8*n1 + sub) + g];
    }
    dft8<1>(z);
    #pragma unroll
    for (int k1 = 1; k1 < 8; k1++) z[k1] = cmul(z[k1], Ti[k1*sub]);
    #pragma unroll
    for (int k1 = 0; k1 < 8; k1++) u2[33*(8*k1 + sub) + g] = z[k1];
    __syncwarp();
    #pragma unroll
    for (int j = 0; j < 8; j++) z[j] = u2[33*(8*sub + j) + g];
    dft8<1>(z);
    __syncwarp();
    #pragma unroll
    for (int k2 = 0; k2 < 8; k2++) u2[33*(sub + 8*k2) + g] = z[k2];
}

__device__ __forceinline__ void ifft_rows(float2* __restrict__ u2, const float2* Ti, int tid,
                                          float2 zres[8])
{
    const int r = tid >> 3, sub = tid & 7;
    float2* R = u2 + 66*r;
    float2 z[8];
    #pragma unroll
    for (int n1 = 0; n1 < 8; n1++) {
        int m = 8*n1 + sub;
        float2 A, B;
        if (m == 0)       { A = make_float2(R[0].x, 0.f);  B = make_float2(R[33].x, 0.f); }
        else if (m == 32) { A = make_float2(R[0].y, 0.f);  B = make_float2(R[33].y, 0.f); }
        else if (m < 32)  { A = R[m];                      B = R[33 + m]; }
        else {
            float2 Am = R[64 - m];      A = make_float2(Am.x, -Am.y);
            float2 Bm = R[33 + 64 - m]; B = make_float2(Bm.x, -Bm.y);
        }
        z[n1] = make_float2(A.x - B.y, A.y + B.x);
    }
    __syncwarp();
    dft8<1>(z);
    #pragma unroll
    for (int k1 = 1; k1 < 8; k1++) z[k1] = cmul(z[k1], Ti[k1*sub]);
    #pragma unroll
    for (int k1 = 0; k1 < 8; k1++) R[8*k1 + sub] = z[k1];
    __syncwarp();
    #pragma unroll
    for (int j = 0; j < 8; j++) z[j] = R[8*sub + j];
    dft8<1>(z);
    #pragma unroll
    for (int k2 = 0; k2 < 8; k2++) zres[k2] = z[k2];
}

__device__ __forceinline__ void fft_rows(const float* __restrict__ pl, int plstride,
                                         float2* __restrict__ u2, const float2* Tf, int tid)
{
    const int r = tid >> 3, sub = tid & 7;
    const float* p0 = pl + (2*r) * plstride;
    const float* p1 = pl + (2*r + 1) * plstride;
    float2* R = u2 + 66*r;
    float2 z[8];
    #pragma unroll
    for (int n1 = 0; n1 < 8; n1++) {
        int m = 8*n1 + sub;
        z[n1] = make_float2(p0[m], p1[m]);
    }
    dft8<-1>(z);
    #pragma unroll
    for (int k1 = 1; k1 < 8; k1++) z[k1] = cmul(z[k1], Tf[k1*sub]);
    #pragma unroll
    for (int k1 = 0; k1 < 8; k1++) R[8*k1 + sub] = z[k1];
    __syncwarp();
    #pragma unroll
    for (int j = 0; j < 8; j++) z[j] = R[8*sub + j];
    dft8<-1>(z);
    __syncwarp();
    #pragma unroll
    for (int k2 = 0; k2 < 8; k2++) R[sub + 8*k2] = z[k2];
    __syncwarp();
    float2 Zk[5], Zm[5];
    #pragma unroll
    for (int q = 0; q < 4; q++) { int k = sub + 8*q; Zk[q] = R[k]; Zm[q] = R[(64 - k) & 63]; }
    if (sub == 0) { Zk[4] = R[32]; Zm[4] = R[32]; }
    __syncwarp();
    #pragma unroll
    for (int q = 0; q < 4; q++) {
        int k = sub + 8*q;
        R[k]      = make_float2(0.5f*(Zk[q].x + Zm[q].x), 0.5f*(Zk[q].y - Zm[q].y));
        R[33 + k] = make_float2(0.5f*(Zk[q].y + Zm[q].y), 0.5f*(Zm[q].x - Zk[q].x));
    }
    if (sub == 0) {
        R[32] = make_float2(Zk[4].x, 0.f);
        R[65] = make_float2(Zk[4].y, 0.f);
    }
}

// Forward FFT along h; finishes IN SMEM: u2[kh*33 + k] = scaled final spectrum.
__device__ __forceinline__ void fft_cols_finish(float2* __restrict__ u2, float2* __restrict__ pc,
                                                const float2* Tf, int tid, float scale)
{
    const int g = tid >> 3, sub = tid & 7;
    float2 z[8];
    if (g == 0) {
        #pragma unroll
        for (int n1 = 0; n1 < 8; n1++) {
            int h = 8*n1 + sub;
            z[n1] = make_float2(u2[33*h].x, u2[33*h + 32].x);
        }
    } else {
        #pragma unroll
        for (int n1 = 0; n1 < 8; n1++) z[n1] = u2[33*(8*n1 + sub) + g];
    }
    dft8<-1>(z);
    #pragma unroll
    for (int k1 = 1; k1 < 8; k1++) z[k1] = cmul(z[k1], Tf[k1*sub]);
    #pragma unroll
    for (int k1 = 0; k1 < 8; k1++) u2[33*(8*k1 + sub) + g] = z[k1];
    __syncwarp();
    #pragma unroll
    for (int j = 0; j < 8; j++) z[j] = u2[33*(8*sub + j) + g];
    dft8<-1>(z);
    __syncwarp();
    if (g != 0) {
        #pragma unroll
        for (int k2 = 0; k2 < 8; k2++) {
            int kh = sub + 8*k2;
            u2[kh*33 + g] = make_float2(z[k2].x * scale, z[k2].y * scale);
        }
    } else {
        #pragma unroll
        for (int k2 = 0; k2 < 8; k2++) pc[sub + 8*k2] = z[k2];
    }
    __syncwarp();
    if (g == 0) {
        #pragma unroll
        for (int j = 0; j < 8; j++) {
            int k = 8*sub + j;
            float2 Zk = pc[k];
            float2 Zm = pc[(64 - k) & 63];
            u2[k*33 + 0]  = make_float2(0.5f*(Zk.x + Zm.x)*scale, 0.5f*(Zk.y - Zm.y)*scale);
            u2[k*33 + 32] = make_float2(0.5f*(Zk.y + Zm.y)*scale, 0.5f*(Zm.x - Zk.x)*scale);
        }
    }
}

// ============================================================
// Split all three weight matrices in one launch: [gate | qkv | proj].
// ============================================================
__global__ __launch_bounds__(256) void split3_kernel(
    const float* __restrict__ wg, const float* __restrict__ wq, const float* __restrict__ wp,
    __nv_bfloat16* __restrict__ hi, __nv_bfloat16* __restrict__ lo)
{
    const int n4g = (CH*CH)/4, n4q = (CH3*CH)/4, n4t = (W_TOTAL)/4;
    int i = blockIdx.x * 256 + threadIdx.x;
    int stride = gridDim.x * 256;
    for (; i < n4t; i += stride) {
        float4 v;
        if (i < n4g)              v = ((const float4*)wg)[i];
        else if (i < n4g + n4q)   v = ((const float4*)wq)[i - n4g];
        else                      v = ((const float4*)wp)[i - n4g - n4q];
        split_store2((__nv_bfloat162*)hi, (__nv_bfloat162*)lo, 2*i,     make_float2(v.x, v.y));
        split_store2((__nv_bfloat162*)hi, (__nv_bfloat162*)lo, 2*i + 1, make_float2(v.z, v.w));
    }
}

// ============================================================
// Split-bf16 tensor-core GEMM (R9, unchanged).
// ============================================================
#define BKt 16
#define APAD 24
#define BPAD 136

template<int MODE>
__global__ __launch_bounds__(256) void mma_gemm(
    const __nv_bfloat16* __restrict__ Ah, const __nv_bfloat16* __restrict__ Al,
    const __nv_bfloat16* __restrict__ Bh, const __nv_bfloat16* __restrict__ Bl,
    const float* __restrict__ bias,
    float* __restrict__ C,
    int M, int Ntot, int K)
{
    __shared__ __align__(16) __nv_bfloat16 sAh[2][128][APAD];
    __shared__ __align__(16) __nv_bfloat16 sAl[2][128][APAD];
    __shared__ __align__(16) __nv_bfloat16 sBh[2][BKt][BPAD];
    __shared__ __align__(16) __nv_bfloat16 sBl[2][BKt][BPAD];

    const int bx = blockIdx.x, by = blockIdx.y, bz = blockIdx.z;
    const int n0 = bx * 128, m0 = by * 128;
    const __nv_bfloat16* Bhp = Bh + (size_t)bz * K * Ntot;
    const __nv_bfloat16* Blp = Bl + (size_t)bz * K * Ntot;
    float* Cp = C + (size_t)bz * M * Ntot;

    const int tid  = threadIdx.x;
    const int lane = tid & 31;
    const int wid  = tid >> 5;
    const int wm   = wid >> 2;
    const int wn   = wid & 3;

    const unsigned uAh = (unsigned)__cvta_generic_to_shared(&sAh[0][0][0]);
    const unsigned uAl = (unsigned)__cvta_generic_to_shared(&sAl[0][0][0]);
    const unsigned uBh = (unsigned)__cvta_generic_to_shared(&sBh[0][0][0]);
    const unsigned uBl = (unsigned)__cvta_generic_to_shared(&sBl[0][0][0]);

    const int arow = tid >> 1;
    const int achk = (tid & 1) * 8;
    const int brow = tid >> 4;
    const int bchk = (tid & 15) * 8;

    auto loadTiles = [&](int k0, int bufI) {
        cp_async16(uAh + (unsigned)(((bufI*128 + arow)*APAD + achk)*2),
                   Ah + (size_t)(m0 + arow) * K + k0 + achk);
        cp_async16(uAl + (unsigned)(((bufI*128 + arow)*APAD + achk)*2),
                   Al + (size_t)(m0 + arow) * K + k0 + achk);
        cp_async16(uBh + (unsigned)(((bufI*BKt + brow)*BPAD + bchk)*2),
                   Bhp + (size_t)(k0 + brow) * Ntot + n0 + bchk);
        cp_async16(uBl + (unsigned)(((bufI*BKt + brow)*BPAD + bchk)*2),
                   Blp + (size_t)(k0 + brow) * Ntot + n0 + bchk);
        cp_commit();
    };

    float acc[4][4][4];
    #pragma unroll
    for (int i = 0; i < 4; i++)
        #pragma unroll
        for (int j = 0; j < 4; j++)
            #pragma unroll
            for (int q = 0; q < 4; q++) acc[i][j][q] = 0.f;

    const unsigned aOff = (unsigned)(((lane & 15) * APAD + (lane >> 4) * 8) * 2);
    const unsigned bOff = (unsigned)(((lane & 15) * BPAD + 32*wn + (lane >> 4) * 8) * 2);

    const int nStages = K / BKt;
    loadTiles(0, 0);
    cp_wait0();
    __syncthreads();

    for (int s = 0; s < nStages; s++) {
        const int buf = s & 1, nxt = buf ^ 1;
        const bool more = (s + 1 < nStages);
        if (more) loadTiles((s + 1) * BKt, nxt);

        unsigned aH[4][4], aL[4][4], bH[2][4], bL[2][4];
        #pragma unroll
        for (int mf = 0; mf < 4; mf++) {
            unsigned rowbase = (unsigned)((buf*128 + 64*wm + 16*mf) * APAD * 2);
            ldsm4(aH[mf], uAh + rowbase + aOff);
            ldsm4(aL[mf], uAl + rowbase + aOff);
        }
        #pragma unroll
        for (int np = 0; np < 2; np++) {
            unsigned cb = (unsigned)((buf*BKt*BPAD + 16*np) * 2);
            ldsm4t(bH[np], uBh + cb + bOff);
            ldsm4t(bL[np], uBl + cb + bOff);
        }
        #pragma unroll
        for (int mf = 0; mf < 4; mf++)
            #pragma unroll
            for (int nf = 0; nf < 4; nf++) {
                const unsigned* bh = &bH[nf >> 1][2*(nf & 1)];
                const unsigned* bl = &bL[nf >> 1][2*(nf & 1)];
                mma16816(acc[mf][nf], aH[mf], bh);
                mma16816(acc[mf][nf], aH[mf], bl);
                mma16816(acc[mf][nf], aL[mf], bh);
            }
        if (more) cp_wait0();
        __syncthreads();
    }

    const int rbase = m0 + 64*wm + (lane >> 2);
    const int cbase = n0 + 32*wn + 2*(lane & 3);
    #pragma unroll
    for (int mf = 0; mf < 4; mf++) {
        #pragma unroll
        for (int half = 0; half < 2; half++) {
            int m = rbase + 16*mf + 8*half;
            float bv = (MODE >= 1) ? bias[m] : 0.f;
            #pragma unroll
            for (int nf = 0; nf < 4; nf++) {
                int c = cbase + 8*nf;
                float vx = acc[mf][nf][2*half + 0] + bv;
                float vy = acc[mf][nf][2*half + 1] + bv;
                if (MODE == 1) {
                    vx = vx / (1.f + __expf(-vx));
                    vy = vy / (1.f + __expf(-vy));
                }
                *(float2*)&Cp[(size_t)m * Ntot + c] = make_float2(vx, vy);
            }
        }
    }
}

// ============================================================
// Forward rfft2 + x-split (R12, unchanged).
// ============================================================
__global__ __launch_bounds__(256) void fft2_fwd_split_kernel(
    const float* __restrict__ in,
    __nv_bfloat162* __restrict__ xh, __nv_bfloat162* __restrict__ xl,
    __nv_bfloat162* __restrict__ outh, __nv_bfloat162* __restrict__ outl,
    float scale)
{
    __shared__ float  sp[HH * 65];
    __shared__ float2 u2[FREQ];
    __shared__ float2 pc[64];
    __shared__ float2 Tf[64];
    const int tid = threadIdx.x;
    const int plane = blockIdx.x;
    const float* p = in + (size_t)plane * NPIX;
    __nv_bfloat162* xhp = xh + (size_t)plane * (NPIX/2);
    __nv_bfloat162* xlp = xl + (size_t)plane * (NPIX/2);

    if (tid < 64) {
        float s, c; sincosf(TWO_PI_OVER_64 * (float)tid, &s, &c);
        Tf[tid] = make_float2(c, -s);
    }
    #pragma unroll
    for (int q = 0; q < 4; q++) {
        int base = tid + 256*q;
        float4 v = ((const float4*)p)[base];
        int row = base >> 4, col = (base & 15) * 4;
        sp[row*65 + col + 0] = v.x;
        sp[row*65 + col + 1] = v.y;
        sp[row*65 + col + 2] = v.z;
        sp[row*65 + col + 3] = v.w;
        split_store2(xhp, xlp, 2*base,     make_float2(v.x, v.y));
        split_store2(xhp, xlp, 2*base + 1, make_float2(v.z, v.w));
    }
    __syncthreads();

    fft_rows(sp, 65, u2, Tf, tid);
    __syncthreads();
    fft_cols_finish(u2, pc, Tf, tid, scale);
    __syncthreads();

    __nv_bfloat162* oh = outh + (size_t)plane * FREQ;
    __nv_bfloat162* ol = outl + (size_t)plane * FREQ;
    for (int i = tid; i < FREQ; i += 256) split_store2(oh, ol, i, u2[i]);
}

// ============================================================
// FULLY FUSED attention middle (steps 4-7):
// conj(q)*k -> irfft2(ortho) -> softmax -> rfft2(bwd) -> conj(A)*v
// -> irfft2(ortho) -> gate-multiply -> bf16 hi/lo split out.
// A-spectrum never leaves shared memory.
// ============================================================
__global__ __launch_bounds__(256) void attn_fused_kernel(
    const float2* __restrict__ qc,
    const float* __restrict__ gate,
    __nv_bfloat162* __restrict__ outh, __nv_bfloat162* __restrict__ outl)
{
    __shared__ float2 y2[FREQ];
    __shared__ float2 u2[FREQ];
    __shared__ float2 pc[64];
    __shared__ float2 Tf[64];
    __shared__ float2 Ti[64];
    __shared__ float  red[256];
    float* pl = (float*)y2;

    const int tid = threadIdx.x;
    const int plane = blockIdx.x;
    const int b  = plane >> 9;
    const int ch = plane & 511;
    const float2* qp = qc + ((size_t)b * CH3 + ch) * FREQ;
    const float2* kp = qc + ((size_t)b * CH3 + 512 + ch) * FREQ;
    const float2* vp = qc + ((size_t)b * CH3 + 1024 + ch) * FREQ;
    const float inv64 = 1.0f / 64.0f;

    if (tid < 64) {
        float s, c; sincosf(TWO_PI_OVER_64 * (float)tid, &s, &c);
        Tf[tid] = make_float2(c, -s);
        Ti[tid] = make_float2(c,  s);
    }
    // Phase 1: Y = conj(q)*k
    for (int i = tid; i < FREQ; i += 256) {
        float2 q = qp[i], k = kp[i];
        y2[i] = make_float2(q.x*k.x + q.y*k.y, q.x*k.y - q.y*k.x);
    }
    __syncthreads();

    // Phase 2-3: irfft2 -> plane
    ifft_cols(y2, u2, Ti, tid);
    __syncthreads();
    {
        float2 zres[8];
        ifft_rows(u2, Ti, tid, zres);
        const int r = tid >> 3, sub = tid & 7;
        __syncthreads();
        #pragma unroll
        for (int k2 = 0; k2 < 8; k2++) {
            int w = sub + 8*k2;
            pl[(2*r)*65 + w]     = zres[k2].x * inv64;
            pl[(2*r + 1)*65 + w] = zres[k2].y * inv64;
        }
    }
    __syncthreads();

    // Phase 4: softmax
    {
        float m = -3.4e38f;
        for (int i = tid; i < NPIX; i += 256) {
            float v = pl[(i >> 6)*65 + (i & 63)];
            m = fmaxf(m, v);
        }
        red[tid] = m; __syncthreads();
        for (int s = 128; s > 0; s >>= 1) { if (tid < s) red[tid] = fmaxf(red[tid], red[tid + s]); __syncthreads(); }
        const float M = red[0];
        __syncthreads();
        float sum = 0.f;
        for (int i = tid; i < NPIX; i += 256) {
            int a = (i >> 6)*65 + (i & 63);
            float e = __expf(pl[a] - M);
            pl[a] = e; sum += e;
        }
        red[tid] = sum; __syncthreads();
        for (int s = 128; s > 0; s >>= 1) { if (tid < s) red[tid] += red[tid + s]; __syncthreads(); }
        const float inv = 1.f / red[0];
        __syncthreads();
        for (int i = tid; i < NPIX; i += 256) {
            int a = (i >> 6)*65 + (i & 63);
            pl[a] *= inv;
        }
    }
    __syncthreads();

    // Phase 5-6: rfft2 (backward norm) -> A spectrum in u2
    fft_rows(pl, 65, u2, Tf, tid);
    __syncthreads();
    fft_cols_finish(u2, pc, Tf, tid, 1.0f);
    __syncthreads();

    // Phase 7: Y = conj(A)*v  (A in u2, v from global) -> y2
    for (int i = tid; i < FREQ; i += 256) {
        float2 a = u2[i], v = vp[i];
        y2[i] = make_float2(a.x*v.x + a.y*v.y, a.x*v.y - a.y*v.x);
    }
    __syncthreads();

    // Phase 8-9: irfft2 -> plane
    ifft_cols(y2, u2, Ti, tid);
    __syncthreads();
    {
        float2 zres[8];
        ifft_rows(u2, Ti, tid, zres);
        __syncthreads();
        const int r = tid >> 3, sub = tid & 7;
        #pragma unroll
        for (int k2 = 0; k2 < 8; k2++) {
            int w = sub + 8*k2;
            pl[(2*r)*65 + w]     = zres[k2].x * inv64;
            pl[(2*r + 1)*65 + w] = zres[k2].y * inv64;
        }
    }
    __syncthreads();

    // Phase 10: gate-multiply + split + coalesced bf162 stores
    {
        const float2* gp2 = (const float2*)(gate + (size_t)plane * NPIX);
        __nv_bfloat162* oh = outh + (size_t)plane * (NPIX/2);
        __nv_bfloat162* ol = outl + (size_t)plane * (NPIX/2);
        for (int i = tid; i < NPIX/2; i += 256) {
            int row = (2*i) >> 6, col = (2*i) & 63;
            float2 g = gp2[i];
            float2 v = make_float2(pl[row*65 + col] * g.x, pl[row*65 + col + 1] * g.y);
            split_store2(oh, ol, i, v);
        }
    }
}

// ============================================================
extern "C" void kernel_launch(void* const* d_in, const int* in_sizes, int n_in,
                              void* d_out, int out_size)
{
    const float* x      = (const float*)d_in[0];
    const float* w_qkv  = (const float*)d_in[1];
    const float* w_gate = (const float*)d_in[2];
    const float* b_gate = (const float*)d_in[3];
    const float* w_proj = (const float*)d_in[4];
    const float* b_proj = (const float*)d_in[5];
    float* out = (float*)d_out;

    float2 *Qc;
    float  *t;
    __nv_bfloat16 *wh, *wl, *bh, *bl, *b2h, *b2l;
    cudaGetSymbolAddress((void**)&Qc,   g_Qc);
    cudaGetSymbolAddress((void**)&t,    g_t);
    cudaGetSymbolAddress((void**)&wh,   g_wh);
    cudaGetSymbolAddress((void**)&wl,   g_wl);
    cudaGetSymbolAddress((void**)&bh,   g_bh);
    cudaGetSymbolAddress((void**)&bl,   g_bl);
    cudaGetSymbolAddress((void**)&b2h,  g_b2h);
    cudaGetSymbolAddress((void**)&b2l,  g_b2l);

    const float inv64 = 1.0f / 64.0f;

    // 1. split all weights in one launch
    split3_kernel<<<1184, 256>>>(w_gate, w_qkv, w_proj, wh, wl);
    // 2. fft2+split: x -> x-split (bh/bl) AND spectrum-split (b2h/b2l)
    fft2_fwd_split_kernel<<<PLANES, 256>>>(x,
        (__nv_bfloat162*)bh, (__nv_bfloat162*)bl,
        (__nv_bfloat162*)b2h, (__nv_bfloat162*)b2l, inv64);
    // 3. gate: t = SiLU(Wg*x + bg)
    {
        dim3 g(NPIX / 128, CH / 128, BATCH);
        mma_gemm<1><<<g, 256>>>(wh + W_GATE_OFF, wl + W_GATE_OFF, bh, bl, b_gate, t, CH, NPIX, CH);
    }
    // 4. QKV GEMM (complex interleaved, Ntot=4224)
    {
        dim3 g(NQKV / 128, CH3 / 128, BATCH);
        mma_gemm<0><<<g, 256>>>(wh + W_QKV_OFF, wl + W_QKV_OFF, b2h, b2l, nullptr, (float*)Qc, CH3, NQKV, CH);
    }
    // 5. fused attention middle (steps 4-7) -> y bf16 split (bh/bl)
    attn_fused_kernel<<<PLANES, 256>>>(Qc, t, (__nv_bfloat162*)bh, (__nv_bfloat162*)bl);
    // 6. proj: out = Wp*y + bp
    {
        dim3 g(NPIX / 128, CH / 128, BATCH);
        mma_gemm<3><<<g, 256>>>(wh + W_PROJ_OFF, wl + W_PROJ_OFF, bh, bl, b_proj, out, CH, NPIX, CH);
    }
}